// round 14
// baseline (speedup 1.0000x reference)
#include <cuda_runtime.h>
#include <cstdint>

typedef unsigned long long ull;

// ---------- packed f32x2 helpers ----------
__device__ __forceinline__ ull f2pack(float lo, float hi) {
    ull r; asm("mov.b64 %0,{%1,%2};" : "=l"(r) : "f"(lo), "f"(hi)); return r;
}
__device__ __forceinline__ void f2unpack(ull a, float& lo, float& hi) {
    asm("mov.b64 {%0,%1},%2;" : "=f"(lo), "=f"(hi) : "l"(a));
}
__device__ __forceinline__ ull f2mul(ull a, ull b) {
    ull r; asm("mul.rn.f32x2 %0,%1,%2;" : "=l"(r) : "l"(a), "l"(b)); return r;
}
__device__ __forceinline__ ull f2add(ull a, ull b) {
    ull r; asm("add.rn.f32x2 %0,%1,%2;" : "=l"(r) : "l"(a), "l"(b)); return r;
}
__device__ __forceinline__ ull f2fma(ull a, ull b, ull c) {
    ull r; asm("fma.rn.f32x2 %0,%1,%2,%3;" : "=l"(r) : "l"(a), "l"(b), "l"(c)); return r;
}

#define TW       64                 // tile width (pair cells); 512/64 = 8 exact
#define TH       86                 // tile height; 6 y-tiles (last guarded) -> 1152 CTAs ~ 2 waves
#define IN_W     74                 // TW + 10
#define TOT_R    96                 // TH + 10 = 6 * 16 exactly -> no runt chunk
#define CHUNK    16
#define NCH      6
#define IN_PITCH 166                // ull per input row ({p,t} 16B cells, >>3 swizzle), even
#define IN_ULL   (CHUNK * IN_PITCH)     // 2656
#define HB_PITCH 67                 // ull per hb row (8B cells, swizzled)
#define SIG_STRIDE (CHUNK * HB_PITCH)   // 1072
#define HB_ULL   (4 * SIG_STRIDE)       // 4288
#define NPIX     12582912.0         // 48 * 512 * 512
#define NBLOCKS  1152               // 8 x 6 x 24

// input swizzle: quad index x + (x>>3) is injective mod 8 under stride-4 sampling
// -> h-phase LDS.128 8-lane phases conflict-free for all k alignments
__device__ __forceinline__ int in_off(int x) { return 2 * x + 2 * (x >> 3); }
__device__ __forceinline__ int c_off(int c)  { return c + (c >> 4); }

// symmetric window: w[d] == w[10-d] (bit-exact on the recovered 1D window)
#define W(d) ws[(d) <= 5 ? (d) : 10 - (d)]

__device__ double        g_acc  = 0.0;
__device__ unsigned int  g_done = 0u;

// dynamic smem: inb[2656] | hb[4288] = 6944 ull = 55552 B -> 4 CTAs/SM
__global__ __launch_bounds__(256, 4) void ssim_main_k(
    const float* __restrict__ pred,
    const float* __restrict__ targ,
    const float* __restrict__ win,
    float* __restrict__ out)
{
    extern __shared__ ull sm[];
    ull* inb = sm;
    ull* hb  = sm + IN_ULL;

    const int tid  = threadIdx.x;
    const int lane = tid & 31;
    const int warp = tid >> 5;

    // --- recover separable symmetric 1D window ---
    float rowsum = 0.f;
#pragma unroll
    for (int j = 0; j < 11; j++) rowsum += __ldg(win + 55 + j);
    const float invr = 1.0f / rowsum;
    ull ws[6];
#pragma unroll
    for (int j = 0; j < 6; j++) {
        float w = __ldg(win + 55 + j) * invr;
        ws[j] = f2pack(w, w);
    }

    const int ox = blockIdx.x * TW;
    const int oy = blockIdx.y * TH;
    const int pz = blockIdx.z;                  // plane pair 0..23
    const float* p0 = pred + (size_t)pz * 524288;
    const float* p1 = p0 + 262144;
    const float* t0 = targ + (size_t)pz * 524288;
    const float* t1 = t0 + 262144;

    // ---- load mapping: fixed column lc, rows lr0, lr0+3, ... ----
    const int lr0   = tid / IN_W;               // 0..3 (3 -> inactive)
    const int lc    = tid - lr0 * IN_W;         // 0..73
    const bool lact = (lr0 < 3);
    const int lgx   = ox - 5 + lc;
    const bool lxin = ((unsigned)lgx < 512u);
    const int linoff = in_off(lc);

    // compute-phase identities
    const int hr   = tid >> 4;                  // h-phase row in chunk (0..15, always dense)
    const int hx0  = (tid & 15) * 4;            // h-phase first output column
    const int hcb  = c_off(hx0);                // hb store base
    const int vc   = tid & 63;                  // v-phase column
    const int vs   = tid >> 6;                  // v-phase signal
    const int ecoff = c_off(tid & 63);          // epilogue column offset (fixed)
    const int er0  = tid >> 6;                  // epilogue row offset, stride 4

    const ull TWO  = f2pack(2.0f, 2.0f);
    const ull NEG1 = f2pack(-1.0f, -1.0f);
    const ull C1p  = f2pack(1e-4f, 1e-4f);
    const ull C2p  = f2pack(9e-4f, 9e-4f);
    const ull C12p = f2pack(1e-4f + 9e-4f, 1e-4f + 9e-4f);
    const ull EPSp = f2pack(1e-8f, 1e-8f);

    // v sliding shift-register accumulators (persist across chunks)
    ull acc[11];
#pragma unroll
    for (int d = 0; d < 11; d++) acc[d] = 0ULL;

    float lsum = 0.f;

    // ---- initial load: chunk 0 ----
    if (lact) {
        for (int r = lr0; r < CHUNK; r += 3) {
            int gy = oy - 5 + r;
            float a0 = 0.f, a1 = 0.f, b0 = 0.f, b1 = 0.f;
            if (lxin && ((unsigned)gy < 512u)) {
                int g = gy * 512 + lgx;
                a0 = __ldg(p0 + g); a1 = __ldg(p1 + g);
                b0 = __ldg(t0 + g); b1 = __ldg(t1 + g);
            }
            *reinterpret_cast<ulonglong2*>(inb + r * IN_PITCH + linoff) =
                make_ulonglong2(f2pack(a0, a1), f2pack(b0, b1));
        }
    }
    __syncthreads();

    for (int ch = 0; ch < NCH; ch++) {
        const int cs = ch * CHUNK;

        // ---- horizontal blur: thread = (row, 4-output x-group); always dense ----
        {
            const ull* rp = inb + hr * IN_PITCH;
            ull am1[4], am2[4], asq[4], apt[4];
#pragma unroll
            for (int j = 0; j < 4; j++) { am1[j]=0ULL; am2[j]=0ULL; asq[j]=0ULL; apt[j]=0ULL; }
#pragma unroll
            for (int k = 0; k < 14; k++) {
                ulonglong2 PT = *reinterpret_cast<const ulonglong2*>(rp + in_off(hx0 + k));
                ull p = PT.x, t = PT.y;
                ull sq = f2fma(p, p, f2mul(t, t));
                ull pt = f2mul(p, t);
#pragma unroll
                for (int j = 0; j < 4; j++) {
                    const int ki = k - j;
                    if (ki >= 0 && ki <= 10) {
                        ull w = W(ki);
                        am1[j] = f2fma(p,  w, am1[j]);
                        am2[j] = f2fma(t,  w, am2[j]);
                        asq[j] = f2fma(sq, w, asq[j]);
                        apt[j] = f2fma(pt, w, apt[j]);
                    }
                }
            }
#pragma unroll
            for (int j = 0; j < 4; j++) {
                int co = hr * HB_PITCH + hcb + j;
                hb[0 * SIG_STRIDE + co] = am1[j];
                hb[1 * SIG_STRIDE + co] = am2[j];
                hb[2 * SIG_STRIDE + co] = asq[j];
                hb[3 * SIG_STRIDE + co] = apt[j];
            }
        }
        __syncthreads();

        // ---- vertical consume: shift-register; overlay outputs into hb ----
        {
            ull* hs = hb + vs * SIG_STRIDE + c_off(vc);
#pragma unroll
            for (int r = 0; r < CHUNK; r++) {
                ull v = hs[r * HB_PITCH];
#pragma unroll
                for (int d = 10; d >= 1; d--) acc[d] = f2fma(v, W(d), acc[d - 1]);
                acc[0] = f2mul(v, W(0));
                if (cs + r >= 10)
                    hs[r * HB_PITCH] = acc[10];   // slot = r (just-consumed row)
            }
        }
        __syncthreads();

        // ---- fused phase: epilogue (hb overlay) + load next chunk (inb) ----
        {
            const int e0   = (cs >= 10) ? cs - 10 : 0;
            int e_hi       = cs + CHUNK - 10;
            const int ymax = 512 - oy;            // y-guard folded into bounds
            if (e_hi > ymax) e_hi = ymax;
            for (int eo = e0 + er0; eo < e_hi; eo += 4) {
                int base = (eo - cs + 10) * HB_PITCH + ecoff;
                ull bm1 = hb[0 * SIG_STRIDE + base];
                ull bm2 = hb[1 * SIG_STRIDE + base];
                ull bsq = hb[2 * SIG_STRIDE + base];
                ull bpt = hb[3 * SIG_STRIDE + base];
                ull m12   = f2mul(bm1, bm2);
                ull den1  = f2fma(bm1, bm1, f2fma(bm2, bm2, C1p));     // mu1^2+mu2^2+C1
                ull den2  = f2fma(den1, NEG1, f2add(bsq, C12p));       // bsq - den1 + C1+C2
                ull sig12 = f2fma(m12,  NEG1, bpt);                    // bpt - m12
                ull num1  = f2fma(m12,   TWO, C1p);
                ull num2  = f2fma(sig12, TWO, C2p);
                ull num   = f2mul(num1, num2);
                ull den   = f2fma(den1, den2, EPSp);
                float n0, n1, d0, d1;
                f2unpack(num, n0, n1);
                f2unpack(den, d0, d1);
                lsum += __fdividef(n0, d0) + __fdividef(n1, d1);
            }
        }

        // load chunk ch+1 into inb
        if (ch < NCH - 1 && lact) {
            const int cs2 = cs + CHUNK;
            for (int r = lr0; r < CHUNK; r += 3) {
                int gy = oy - 5 + cs2 + r;
                float a0 = 0.f, a1 = 0.f, b0 = 0.f, b1 = 0.f;
                if (lxin && ((unsigned)gy < 512u)) {
                    int g = gy * 512 + lgx;
                    a0 = __ldg(p0 + g); a1 = __ldg(p1 + g);
                    b0 = __ldg(t0 + g); b1 = __ldg(t1 + g);
                }
                *reinterpret_cast<ulonglong2*>(inb + r * IN_PITCH + linoff) =
                    make_ulonglong2(f2pack(a0, a1), f2pack(b0, b1));
            }
        }
        __syncthreads();
    }

    // --- block reduction -> double atomic + last-block finalize ---
#pragma unroll
    for (int o = 16; o; o >>= 1) lsum += __shfl_xor_sync(0xffffffffu, lsum, o);
    __shared__ float warp_part[8];
    if (lane == 0) warp_part[warp] = lsum;
    __syncthreads();
    if (tid == 0) {
        float v = 0.f;
#pragma unroll
        for (int i = 0; i < 8; i++) v += warp_part[i];
        atomicAdd(&g_acc, (double)v);
        __threadfence();
        unsigned int old = atomicAdd(&g_done, 1u);
        if (old == NBLOCKS - 1u) {
            __threadfence();
            double total = *((volatile double*)&g_acc);
            out[0] = 1.0f - (float)(total * (1.0 / NPIX));
            g_acc  = 0.0;
            g_done = 0u;
        }
    }
}

extern "C" void kernel_launch(void* const* d_in, const int* in_sizes, int n_in,
                              void* d_out, int out_size)
{
    const float* pred = (const float*)d_in[0];
    const float* targ = (const float*)d_in[1];
    const float* win  = (const float*)d_in[2];
    float* out = (float*)d_out;

    const int smem_bytes = (IN_ULL + HB_ULL) * 8;   // 55552
    cudaFuncSetAttribute(ssim_main_k, cudaFuncAttributeMaxDynamicSharedMemorySize, smem_bytes);

    dim3 grid(8, 6, 24), blk(256);
    ssim_main_k<<<grid, blk, smem_bytes>>>(pred, targ, win, out);
}

// round 16
// speedup vs baseline: 1.5088x; 1.5088x over previous
#include <cuda_runtime.h>
#include <cstdint>

typedef unsigned long long ull;

// ---------- packed f32x2 helpers ----------
__device__ __forceinline__ ull f2pack(float lo, float hi) {
    ull r; asm("mov.b64 %0,{%1,%2};" : "=l"(r) : "f"(lo), "f"(hi)); return r;
}
__device__ __forceinline__ void f2unpack(ull a, float& lo, float& hi) {
    asm("mov.b64 {%0,%1},%2;" : "=f"(lo), "=f"(hi) : "l"(a));
}
__device__ __forceinline__ ull f2mul(ull a, ull b) {
    ull r; asm("mul.rn.f32x2 %0,%1,%2;" : "=l"(r) : "l"(a), "l"(b)); return r;
}
__device__ __forceinline__ ull f2add(ull a, ull b) {
    ull r; asm("add.rn.f32x2 %0,%1,%2;" : "=l"(r) : "l"(a), "l"(b)); return r;
}
__device__ __forceinline__ ull f2fma(ull a, ull b, ull c) {
    ull r; asm("fma.rn.f32x2 %0,%1,%2,%3;" : "=l"(r) : "l"(a), "l"(b), "l"(c)); return r;
}

#define TW       64                 // tile width; 512/64 = 8 exact
#define TH       86                 // 6 y-tiles -> 1152 CTAs = 2 full waves
#define IN_W     74                 // TW + 10
#define TOT_R    96                 // TH + 10 = 6*15 + 6 (runt)
#define CHUNK    15
#define IN_PITCH 184                // ull per input row ({p,t} 16B cells, >>2 swizzle) - PROVEN CF
#define IN_ULL   (CHUNK * IN_PITCH)     // 2760
#define HB_PITCH 67                 // ull per hb row (8B cells, c+(c>>4)) - PROVEN CF
#define SIG_STRIDE (CHUNK * HB_PITCH)   // 1005
#define HB_ULL   (4 * SIG_STRIDE)       // 4020
#define NPIX     12582912.0         // 48 * 512 * 512
#define NBLOCKS  1152               // 8 x 6 x 24

// proven swizzles (R13): quad q = x + (x>>2) -> 5i mod 8 permutation per phase
__device__ __forceinline__ int in_off(int x) { return 2 * x + 2 * (x >> 2); }
__device__ __forceinline__ int c_off(int c)  { return c + (c >> 4); }

// symmetric window: w[d] == w[10-d] (bit-exact on the recovered 1D window)
#define W(d) ws[(d) <= 5 ? (d) : 10 - (d)]

__device__ double        g_acc  = 0.0;
__device__ unsigned int  g_done = 0u;

// ---- horizontal blur for one chunk: NR rows valid (compile-time) ----
template<int NR>
__device__ __forceinline__ void h_blur(const ull* __restrict__ inb, ull* __restrict__ hb,
                                       int hr, int hx0, int hcb, const ull* __restrict__ ws)
{
    if (NR == CHUNK ? (hr < CHUNK) : (hr < NR)) {
        const ull* rp = inb + hr * IN_PITCH;
        ull am1[4], am2[4], asq[4], apt[4];
#pragma unroll
        for (int j = 0; j < 4; j++) { am1[j]=0ULL; am2[j]=0ULL; asq[j]=0ULL; apt[j]=0ULL; }
#pragma unroll
        for (int k = 0; k < 14; k++) {
            ulonglong2 PT = *reinterpret_cast<const ulonglong2*>(rp + in_off(hx0 + k));
            ull p = PT.x, t = PT.y;
            ull sq = f2fma(p, p, f2mul(t, t));
            ull pt = f2mul(p, t);
#pragma unroll
            for (int j = 0; j < 4; j++) {
                const int ki = k - j;
                if (ki >= 0 && ki <= 10) {
                    ull w = W(ki);
                    am1[j] = f2fma(p,  w, am1[j]);
                    am2[j] = f2fma(t,  w, am2[j]);
                    asq[j] = f2fma(sq, w, asq[j]);
                    apt[j] = f2fma(pt, w, apt[j]);
                }
            }
        }
#pragma unroll
        for (int j = 0; j < 4; j++) {
            int co = hr * HB_PITCH + hcb + j;
            hb[0 * SIG_STRIDE + co] = am1[j];
            hb[1 * SIG_STRIDE + co] = am2[j];
            hb[2 * SIG_STRIDE + co] = asq[j];
            hb[3 * SIG_STRIDE + co] = apt[j];
        }
    }
}

// ---- vertical consume: NR rows; GUARD10 = store only rows with global idx >= 10 ----
template<int NR, bool GUARD10>
__device__ __forceinline__ void v_consume(ull* __restrict__ hs, ull acc[11],
                                          const ull* __restrict__ ws)
{
#pragma unroll
    for (int r = 0; r < NR; r++) {
        ull v = hs[r * HB_PITCH];
#pragma unroll
        for (int d = 10; d >= 1; d--) acc[d] = f2fma(v, W(d), acc[d - 1]);
        acc[0] = f2mul(v, W(0));
        if (!GUARD10 || r >= 10)
            hs[r * HB_PITCH] = acc[10];   // overlay into just-consumed slot (race-free)
    }
}

// ---- epilogue over output rows [e0, e_hi), slot = eo - cs + 10 ----
__device__ __forceinline__ void epilogue(const ull* __restrict__ hb, float& lsum,
                                         int cs, int e0, int e_hi, int er0, int ecoff)
{
    const ull TWO  = f2pack(2.0f, 2.0f);
    const ull NEG1 = f2pack(-1.0f, -1.0f);
    const ull C1p  = f2pack(1e-4f, 1e-4f);
    const ull C2p  = f2pack(9e-4f, 9e-4f);
    const ull C12p = f2pack(1e-4f + 9e-4f, 1e-4f + 9e-4f);
    const ull EPSp = f2pack(1e-8f, 1e-8f);

    for (int eo = e0 + er0; eo < e_hi; eo += 4) {
        int base = (eo - cs + 10) * HB_PITCH + ecoff;
        ull bm1 = hb[0 * SIG_STRIDE + base];
        ull bm2 = hb[1 * SIG_STRIDE + base];
        ull bsq = hb[2 * SIG_STRIDE + base];
        ull bpt = hb[3 * SIG_STRIDE + base];
        ull m12   = f2mul(bm1, bm2);
        ull den1  = f2fma(bm1, bm1, f2fma(bm2, bm2, C1p));     // mu1^2+mu2^2+C1
        ull den2  = f2fma(den1, NEG1, f2add(bsq, C12p));       // bsq - den1 + C1+C2
        ull sig12 = f2fma(m12,  NEG1, bpt);                    // bpt - m12
        ull num1  = f2fma(m12,   TWO, C1p);
        ull num2  = f2fma(sig12, TWO, C2p);
        ull num   = f2mul(num1, num2);
        ull den   = f2fma(den1, den2, EPSp);
        float n0, n1, d0, d1;
        f2unpack(num, n0, n1);
        f2unpack(den, d0, d1);
        lsum += __fdividef(n0, d0) + __fdividef(n1, d1);
    }
}

// dynamic smem: inb[2760] | hb[4020] = 6780 ull = 54240 B -> 4 CTAs/SM
__global__ __launch_bounds__(256, 4) void ssim_main_k(
    const float* __restrict__ pred,
    const float* __restrict__ targ,
    const float* __restrict__ win,
    float* __restrict__ out)
{
    extern __shared__ ull sm[];
    ull* inb = sm;
    ull* hb  = sm + IN_ULL;

    const int tid  = threadIdx.x;
    const int lane = tid & 31;
    const int warp = tid >> 5;

    // --- recover separable symmetric 1D window ---
    float rowsum = 0.f;
#pragma unroll
    for (int j = 0; j < 11; j++) rowsum += __ldg(win + 55 + j);
    const float invr = 1.0f / rowsum;
    ull ws[6];
#pragma unroll
    for (int j = 0; j < 6; j++) {
        float w = __ldg(win + 55 + j) * invr;
        ws[j] = f2pack(w, w);
    }

    const int ox = blockIdx.x * TW;
    const int oy = blockIdx.y * TH;
    const int pz = blockIdx.z;                  // plane pair 0..23
    const float* p0 = pred + (size_t)pz * 524288;
    const float* p1 = p0 + 262144;
    const float* t0 = targ + (size_t)pz * 524288;
    const float* t1 = t0 + 262144;

    // ---- load mapping: fixed column lc, rows lr0, lr0+3, ... ----
    const int lr0   = tid / IN_W;               // 0..3 (3 -> inactive)
    const int lc    = tid - lr0 * IN_W;         // 0..73
    const bool lact = (lr0 < 3);
    const int lgx   = ox - 5 + lc;
    const bool lxin = ((unsigned)lgx < 512u);
    const int linoff = in_off(lc);

    // compute-phase identities
    const int hr   = tid >> 4;                  // h-phase row in chunk (0..15)
    const int hx0  = (tid & 15) * 4;            // h-phase first output column
    const int hcb  = c_off(hx0);                // hb store base
    const int vc   = tid & 63;                  // v-phase column
    const int vs   = tid >> 6;                  // v-phase signal
    const int ecoff = c_off(tid & 63);          // epilogue column offset
    const int er0  = tid >> 6;                  // epilogue row offset, stride 4

    ull* hs = hb + vs * SIG_STRIDE + c_off(vc); // this thread's v-column base

    // v sliding shift-register accumulators (persist across chunks)
    ull acc[11];
#pragma unroll
    for (int d = 0; d < 11; d++) acc[d] = 0ULL;

    float lsum = 0.f;

    // ---- loader helper (runtime row bound; loader is cheap) ----
    auto load_rows = [&](int row_base, int nr) {
        if (lact) {
            for (int r = lr0; r < nr; r += 3) {
                int gy = oy - 5 + row_base + r;
                float a0 = 0.f, a1 = 0.f, b0 = 0.f, b1 = 0.f;
                if (lxin && ((unsigned)gy < 512u)) {
                    int g = gy * 512 + lgx;
                    a0 = __ldg(p0 + g); a1 = __ldg(p1 + g);
                    b0 = __ldg(t0 + g); b1 = __ldg(t1 + g);
                }
                *reinterpret_cast<ulonglong2*>(inb + r * IN_PITCH + linoff) =
                    make_ulonglong2(f2pack(a0, a1), f2pack(b0, b1));
            }
        }
    };

    // ---- prologue: load chunk 0 ----
    load_rows(0, CHUNK);
    __syncthreads();

    // ======== chunk 0 (cs = 0): guarded v-stores, short epilogue ========
    h_blur<CHUNK>(inb, hb, hr, hx0, hcb, ws);
    __syncthreads();
    v_consume<CHUNK, true>(hs, acc, ws);
    __syncthreads();
    epilogue(hb, lsum, 0, 0, 5, er0, ecoff);
    load_rows(CHUNK, CHUNK);
    __syncthreads();

    // ======== chunks 1..5: fully dense, no guards ========
    for (int ch = 1; ch <= 5; ch++) {
        const int cs = ch * CHUNK;
        h_blur<CHUNK>(inb, hb, hr, hx0, hcb, ws);
        __syncthreads();
        v_consume<CHUNK, false>(hs, acc, ws);
        __syncthreads();
        epilogue(hb, lsum, cs, cs - 10, cs + 5, er0, ecoff);
        load_rows(cs + CHUNK, (ch == 5) ? (TOT_R - 6 * CHUNK) : CHUNK);
        __syncthreads();
    }

    // ======== runt chunk (cs = 90, 6 rows) ========
    {
        const int cs = 6 * CHUNK;                 // 90
        h_blur<TOT_R - 6 * CHUNK>(inb, hb, hr, hx0, hcb, ws);
        __syncthreads();
        v_consume<TOT_R - 6 * CHUNK, false>(hs, acc, ws);
        __syncthreads();
        int e_hi = cs + (TOT_R - 6 * CHUNK) - 10; // 86
        const int ymax = 512 - oy;                // >= 82 always; clamp only here
        if (e_hi > ymax) e_hi = ymax;
        epilogue(hb, lsum, cs, cs - 10, e_hi, er0, ecoff);
    }

    // --- block reduction -> double atomic + last-block finalize ---
#pragma unroll
    for (int o = 16; o; o >>= 1) lsum += __shfl_xor_sync(0xffffffffu, lsum, o);
    __shared__ float warp_part[8];
    if (lane == 0) warp_part[warp] = lsum;
    __syncthreads();
    if (tid == 0) {
        float v = 0.f;
#pragma unroll
        for (int i = 0; i < 8; i++) v += warp_part[i];
        atomicAdd(&g_acc, (double)v);
        __threadfence();
        unsigned int old = atomicAdd(&g_done, 1u);
        if (old == NBLOCKS - 1u) {
            __threadfence();
            double total = *((volatile double*)&g_acc);
            out[0] = 1.0f - (float)(total * (1.0 / NPIX));
            g_acc  = 0.0;
            g_done = 0u;
        }
    }
}

extern "C" void kernel_launch(void* const* d_in, const int* in_sizes, int n_in,
                              void* d_out, int out_size)
{
    const float* pred = (const float*)d_in[0];
    const float* targ = (const float*)d_in[1];
    const float* win  = (const float*)d_in[2];
    float* out = (float*)d_out;

    const int smem_bytes = (IN_ULL + HB_ULL) * 8;   // 54240
    cudaFuncSetAttribute(ssim_main_k, cudaFuncAttributeMaxDynamicSharedMemorySize, smem_bytes);

    dim3 grid(8, 6, 24), blk(256);
    ssim_main_k<<<grid, blk, smem_bytes>>>(pred, targ, win, out);
}